// round 10
// baseline (speedup 1.0000x reference)
#include <cuda_runtime.h>
#include <cuda_bf16.h>
#include <cstdint>

#define BATCH 2048
#define DIM   1024
#define HID   1024
#define STEPS 32
#define ROWS  (STEPS*BATCH)   /* 65536 */

// Output layout (float32, concatenated in reference return order)
#define OUT_FINAL   0
#define OUT_DELTA   (BATCH*DIM)                  /* 2097152 */
#define OUT_TLOG    (OUT_DELTA + STEPS*BATCH)    /* 2162688 */
#define OUT_VINIT   (OUT_TLOG + BATCH)           /* 2164736 */

// ---------------- device scratch (static globals: allocation-free) ----------
__device__ __align__(256) __nv_bfloat16 g_W1[DIM*HID];   // row-major [k][n]
__device__ __align__(256) __nv_bfloat16 g_W2[HID*HID];
__device__ __align__(256) __nv_bfloat16 g_W3[HID*DIM];
__device__ __align__(256) __nv_bfloat16 g_X0[(size_t)BATCH*DIM];
__device__ __align__(256) float         g_Z1[(size_t)BATCH*HID];
__device__ __align__(256) __nv_bfloat16 g_H1[(size_t)ROWS*HID];
__device__ __align__(256) __nv_bfloat16 g_H2[(size_t)ROWS*HID];
__device__ float g_sum[ROWS];    // per-row sum(exp(logit))
__device__ float g_tl [ROWS];    // per-row target logit

// ---------------- helpers -----------------------------------------------------
__device__ __forceinline__ uint32_t smem_u32(const void* p) {
    return (uint32_t)__cvta_generic_to_shared(p);
}
__device__ __forceinline__ void cp_async16(uint32_t s, const void* g) {
    asm volatile("cp.async.cg.shared.global [%0], [%1], 16;\n" :: "r"(s), "l"(g) : "memory");
}
__device__ __forceinline__ void cp_commit() {
    asm volatile("cp.async.commit_group;\n" ::: "memory");
}
template <int N>
__device__ __forceinline__ void cp_wait() {
    asm volatile("cp.async.wait_group %0;\n" :: "n"(N) : "memory");
}
__device__ __forceinline__ void ldsm_x4(uint32_t& r0, uint32_t& r1, uint32_t& r2,
                                        uint32_t& r3, uint32_t addr) {
    asm volatile("ldmatrix.sync.aligned.m8n8.x4.shared.b16 {%0,%1,%2,%3}, [%4];\n"
                 : "=r"(r0), "=r"(r1), "=r"(r2), "=r"(r3) : "r"(addr));
}
__device__ __forceinline__ void ldsm_x4_t(uint32_t& r0, uint32_t& r1, uint32_t& r2,
                                          uint32_t& r3, uint32_t addr) {
    asm volatile("ldmatrix.sync.aligned.m8n8.x4.trans.shared.b16 {%0,%1,%2,%3}, [%4];\n"
                 : "=r"(r0), "=r"(r1), "=r"(r2), "=r"(r3) : "r"(addr));
}
__device__ __forceinline__ void mma16816(float* c, const uint32_t* a, const uint32_t* b) {
    asm volatile("mma.sync.aligned.m16n8k16.row.col.f32.bf16.bf16.f32 "
                 "{%0,%1,%2,%3}, {%4,%5,%6,%7}, {%8,%9}, {%0,%1,%2,%3};\n"
                 : "+f"(c[0]), "+f"(c[1]), "+f"(c[2]), "+f"(c[3])
                 : "r"(a[0]), "r"(a[1]), "r"(a[2]), "r"(a[3]), "r"(b[0]), "r"(b[1]));
}

// ---------------- prep kernels --------------------------------------------------
__global__ void convert_weights_kernel(const float* __restrict__ W1,
                                       const float* __restrict__ W2,
                                       const float* __restrict__ W3) {
    int i = blockIdx.x * 256 + threadIdx.x;
    if (i < DIM * HID) {
        g_W1[i] = __float2bfloat16(W1[i]);
        g_W2[i] = __float2bfloat16(W2[i]);
        g_W3[i] = __float2bfloat16(W3[i]);
    }
}
__global__ void expand0_kernel(const float* __restrict__ init) {
    int i = blockIdx.x * 256 + threadIdx.x;
    if (i < BATCH * DIM) g_X0[i] = __float2bfloat16(init[i]);
}
// zero g_sum and emit delta output (both trivially parallel)
__global__ void prep_kernel(const int* __restrict__ tpos, float* __restrict__ out) {
    int i = blockIdx.x * 256 + threadIdx.x;
    if (i < ROWS) {
        g_sum[i] = 0.f;
        out[OUT_DELTA + i] = (float)tpos[i];
    }
}

// ---------------- proven GEMM config, now with 3-stage pipeline ----------------
// BM=BN=128 BK=64, 256 threads (4 M-warps x 2 N-warps, 32x64 warp tile),
// 3 smem stages + wait_group<1> steady state, 2 CTAs/SM.
// MODE 0: fp32 raw out (z1 base, no bias)
// MODE 2: bf16 relu(A@W + bias) out (layer 2)
// MODE 3: fused log-softmax stats (layer 3): g_sum[row] += sum(exp(logit));
//         g_tl[row] = logit[tpos[row]]. No logits store.
#define NSTG 3
#define GEMM_SMEM_BYTES (NSTG*(128*72*2 + 64*136*2))   /* 107520 */

template <int MODE>
__global__ __launch_bounds__(256, 2)
void gemm_kernel(const __nv_bfloat16* __restrict__ A,
                 const __nv_bfloat16* __restrict__ W,
                 const float* __restrict__ bias,
                 __nv_bfloat16* __restrict__ outB,
                 float* __restrict__ outF,
                 const int* __restrict__ tpos) {
    constexpr int N = 1024, K = 1024, BM = 128, BK = 64, AP = 72, BP = 136;
    constexpr int NK = K / BK;   // 16
    extern __shared__ char smem_raw[];
    typedef __nv_bfloat16 bf;
    bf (*As)[BM][AP] = (bf(*)[BM][AP])smem_raw;
    bf (*Bs)[BK][BP] = (bf(*)[BK][BP])(smem_raw + NSTG * BM * AP * sizeof(bf));
    __shared__ float sbias[128];
    __shared__ int stpos[128];

    const int rowBase = blockIdx.y * BM, colBase = blockIdx.x * 128;
    const int tid = threadIdx.x, lane = tid & 31, warp = tid >> 5;
    const int wm = (warp & 3) * 32, wn = (warp >> 2) * 64;
    const int lr = lane & 15, lc8 = (lane >> 4) << 3;

    if (MODE != 0 && tid < 128) sbias[tid] = bias[colBase + tid];
    if (MODE == 3 && tid < 128) stpos[tid] = tpos[rowBase + tid];

    float c[2][8][4];
#pragma unroll
    for (int i = 0; i < 2; i++)
#pragma unroll
        for (int j = 0; j < 8; j++)
#pragma unroll
            for (int k = 0; k < 4; k++) c[i][j][k] = 0.f;

    auto loadTiles = [&](int kt, int buf) {
#pragma unroll
        for (int i = 0; i < 4; i++) {
            int ch = tid + i * 256;
            int row = ch >> 3, kk = ch & 7;
            cp_async16(smem_u32(&As[buf][row][kk * 8]),
                       A + (size_t)(rowBase + row) * K + kt * BK + kk * 8);
            int br = ch >> 4, n8 = ch & 15;
            cp_async16(smem_u32(&Bs[buf][br][n8 * 8]),
                       W + (size_t)(kt * BK + br) * N + colBase + n8 * 8);
        }
    };
    loadTiles(0, 0); cp_commit();
    loadTiles(1, 1); cp_commit();

    for (int kt = 0; kt < NK; ++kt) {
        if (kt == NK - 1) cp_wait<0>(); else cp_wait<1>();
        __syncthreads();
        if (kt + 2 < NK) { loadTiles(kt + 2, (kt + 2) % NSTG); cp_commit(); }
        const int buf = kt % NSTG;
#pragma unroll
        for (int kp = 0; kp < 4; kp++) {
            uint32_t a[2][4];
#pragma unroll
            for (int mi = 0; mi < 2; mi++)
                ldsm_x4(a[mi][0], a[mi][1], a[mi][2], a[mi][3],
                        smem_u32(&As[buf][wm + mi * 16 + lr][kp * 16 + lc8]));
            uint32_t b[8][2];
#pragma unroll
            for (int nj = 0; nj < 4; nj++) {
                uint32_t t0, t1, t2, t3;
                ldsm_x4_t(t0, t1, t2, t3,
                          smem_u32(&Bs[buf][kp * 16 + lr][wn + nj * 16 + lc8]));
                b[2 * nj][0] = t0; b[2 * nj][1] = t1;
                b[2 * nj + 1][0] = t2; b[2 * nj + 1][1] = t3;
            }
#pragma unroll
            for (int mi = 0; mi < 2; mi++)
#pragma unroll
                for (int ni = 0; ni < 8; ni++) mma16816(c[mi][ni], a[mi], b[ni]);
        }
    }

    if (MODE == 0) {
#pragma unroll
        for (int mi = 0; mi < 2; mi++)
#pragma unroll
            for (int ni = 0; ni < 8; ni++) {
                int col = colBase + wn + ni * 8 + (lane & 3) * 2;
                int r0 = rowBase + wm + mi * 16 + (lane >> 2);
                *(float2*)(outF + (size_t)r0 * N + col) =
                    make_float2(c[mi][ni][0], c[mi][ni][1]);
                *(float2*)(outF + (size_t)(r0 + 8) * N + col) =
                    make_float2(c[mi][ni][2], c[mi][ni][3]);
            }
    } else if (MODE == 2) {
#pragma unroll
        for (int mi = 0; mi < 2; mi++)
#pragma unroll
            for (int ni = 0; ni < 8; ni++) {
                int cl = wn + ni * 8 + (lane & 3) * 2;
                int col = colBase + cl;
                float bi0 = sbias[cl], bi1 = sbias[cl + 1];
                int r0 = rowBase + wm + mi * 16 + (lane >> 2);
                float x0 = fmaxf(c[mi][ni][0] + bi0, 0.f);
                float x1 = fmaxf(c[mi][ni][1] + bi1, 0.f);
                float x2 = fmaxf(c[mi][ni][2] + bi0, 0.f);
                float x3 = fmaxf(c[mi][ni][3] + bi1, 0.f);
                *(__nv_bfloat162*)(outB + (size_t)r0 * N + col) =
                    __floats2bfloat162_rn(x0, x1);
                *(__nv_bfloat162*)(outB + (size_t)(r0 + 8) * N + col) =
                    __floats2bfloat162_rn(x2, x3);
            }
    } else {
        // fused softmax stats: per-row sum of exp(logit) + target-logit gather.
        // logits are small (|z| < ~4): exp without max-subtraction is safe in fp32.
        float rsum[4];
#pragma unroll
        for (int i = 0; i < 4; i++) rsum[i] = 0.f;
#pragma unroll
        for (int mi = 0; mi < 2; mi++) {
            const int rA = rowBase + wm + mi * 16 + (lane >> 2);   // rows rA, rA+8
            const int pA = stpos[rA - rowBase];
            const int pB = stpos[rA + 8 - rowBase];
            const int cA = pA - colBase - wn;
            const int cB = pB - colBase - wn;
#pragma unroll
            for (int ni = 0; ni < 8; ni++) {
                int cl = wn + ni * 8 + (lane & 3) * 2;
                float bi0 = sbias[cl], bi1 = sbias[cl + 1];
                float x0 = c[mi][ni][0] + bi0, x1 = c[mi][ni][1] + bi1;
                float x2 = c[mi][ni][2] + bi0, x3 = c[mi][ni][3] + bi1;
                rsum[mi * 2]     += __expf(x0) + __expf(x1);
                rsum[mi * 2 + 1] += __expf(x2) + __expf(x3);
                // target gather: unique owner thread writes
                if ((cA >> 3) == ni && ((cA >> 1) & 3) == (lane & 3))
                    g_tl[rA] = (cA & 1) ? x1 : x0;
                if ((cB >> 3) == ni && ((cB >> 1) & 3) == (lane & 3))
                    g_tl[rA + 8] = (cB & 1) ? x3 : x2;
            }
        }
        // quad reduce (lanes sharing a row are lane^1, lane^2)
#pragma unroll
        for (int i = 0; i < 4; i++) {
            rsum[i] += __shfl_xor_sync(0xffffffffu, rsum[i], 1);
            rsum[i] += __shfl_xor_sync(0xffffffffu, rsum[i], 2);
        }
        if ((lane & 3) == 0) {
#pragma unroll
            for (int mi = 0; mi < 2; mi++) {
                int rA = rowBase + wm + mi * 16 + (lane >> 2);
                atomicAdd(&g_sum[rA], rsum[mi * 2]);
                atomicAdd(&g_sum[rA + 8], rsum[mi * 2 + 1]);
            }
        }
    }
}

// ---------------- incremental layer-1: H1 for all 32 steps (sync-free loop) ---
__global__ __launch_bounds__(256)
void h1_kernel(const float* __restrict__ init,
               const int* __restrict__ tpos,
               const float* __restrict__ b1) {
    const int b = blockIdx.x;
    const int tid = threadIdx.x;
    __shared__ unsigned char bits[DIM];
    __shared__ int   s_p[STEPS];
    __shared__ float s_sign[STEPS];

    float z[4], bb[4];
#pragma unroll
    for (int k = 0; k < 4; k++) {
        int col = tid + k * 256;
        z[k] = g_Z1[(size_t)b * HID + col];
        bb[k] = b1[col];
    }
    for (int i = tid; i < DIM; i += 256)
        bits[i] = (unsigned char)(init[(size_t)b * DIM + i] > 0.5f);
    __syncthreads();
    // precompute the full flip schedule once (tiny sequential pass)
    if (tid == 0) {
        for (int t = 0; t < STEPS; t++) {
            int p = tpos[t * BATCH + b];
            s_p[t] = p;
            s_sign[t] = 1.f - 2.f * (float)bits[p];
            bits[p] ^= 1;
        }
    }
    __syncthreads();
    // sync-free main loop: each thread owns its 4 z columns
    for (int t = 0; t < STEPS; t++) {
        const int row = t * BATCH + b;
        __nv_bfloat16* dst = g_H1 + (size_t)row * HID;
#pragma unroll
        for (int k = 0; k < 4; k++) {
            int col = tid + k * 256;
            dst[col] = __float2bfloat16(fmaxf(z[k] + bb[k], 0.f));
        }
        const int p = s_p[t];
        const float sg = s_sign[t];
        const __nv_bfloat16* wrow = g_W1 + (size_t)p * HID;
#pragma unroll
        for (int k = 0; k < 4; k++) {
            int col = tid + k * 256;
            z[k] += sg * __bfloat162float(wrow[col]);
        }
    }
}

// ---------------- assemble outputs --------------------------------------------
__global__ void finalize_kernel(const float* __restrict__ init,
                                const int* __restrict__ tpos,
                                float* __restrict__ out) {
    int b = blockIdx.x;
    const float* src = init + (size_t)b * DIM;
    float* frow = out + OUT_FINAL + (size_t)b * DIM;
    float* vrow = out + OUT_VINIT + (size_t)b * DIM;
    for (int i = threadIdx.x; i < DIM; i += blockDim.x) {
        float v = src[i];
        frow[i] = v;
        vrow[i] = v;
    }
    __syncthreads();
    if (threadIdx.x == 0) {
        for (int s = 0; s < STEPS; s++) {
            int p = tpos[s * BATCH + b];
            frow[p] = 1.0f - frow[p];
        }
        float acc = 0.f;
        for (int t = 0; t < STEPS; t++) {
            int r = t * BATCH + b;
            acc += g_tl[r] - __logf(g_sum[r]);
        }
        out[OUT_TLOG + b] = acc;
    }
}

// ---------------- launch --------------------------------------------------------
extern "C" void kernel_launch(void* const* d_in, const int* in_sizes, int n_in,
                              void* d_out, int out_size) {
    const float* init = (const float*)d_in[0];
    const int*   tpos = (const int*)d_in[1];
    const float* W1   = (const float*)d_in[2];
    const float* b1   = (const float*)d_in[3];
    const float* W2   = (const float*)d_in[4];
    const float* b2   = (const float*)d_in[5];
    const float* W3   = (const float*)d_in[6];
    const float* b3   = (const float*)d_in[7];
    float* out = (float*)d_out;

    static __nv_bfloat16 *pW1 = nullptr, *pW2, *pW3, *pX0, *pH1, *pH2;
    static float *pZ1;
    if (!pW1) {
        cudaGetSymbolAddress((void**)&pW1, g_W1);
        cudaGetSymbolAddress((void**)&pW2, g_W2);
        cudaGetSymbolAddress((void**)&pW3, g_W3);
        cudaGetSymbolAddress((void**)&pX0, g_X0);
        cudaGetSymbolAddress((void**)&pH1, g_H1);
        cudaGetSymbolAddress((void**)&pH2, g_H2);
        cudaGetSymbolAddress((void**)&pZ1, g_Z1);
        cudaFuncSetAttribute(gemm_kernel<0>,
            cudaFuncAttributeMaxDynamicSharedMemorySize, GEMM_SMEM_BYTES);
        cudaFuncSetAttribute(gemm_kernel<2>,
            cudaFuncAttributeMaxDynamicSharedMemorySize, GEMM_SMEM_BYTES);
        cudaFuncSetAttribute(gemm_kernel<3>,
            cudaFuncAttributeMaxDynamicSharedMemorySize, GEMM_SMEM_BYTES);
    }

    convert_weights_kernel<<<(DIM * HID + 255) / 256, 256>>>(W1, W2, W3);
    expand0_kernel<<<(BATCH * DIM + 255) / 256, 256>>>(init);
    prep_kernel<<<(ROWS + 255) / 256, 256>>>(tpos, out);

    // z1_base = X0 @ W1 (fp32 raw)
    gemm_kernel<0><<<dim3(8, BATCH / 128), 256, GEMM_SMEM_BYTES>>>(
        pX0, pW1, nullptr, nullptr, pZ1, nullptr);
    // incremental layer 1
    h1_kernel<<<BATCH, 256>>>(init, tpos, b1);
    // layer 2: H2 = relu(H1 @ W2 + b2)
    gemm_kernel<2><<<dim3(8, ROWS / 128), 256, GEMM_SMEM_BYTES>>>(
        pH1, pW2, b2, pH2, nullptr, nullptr);
    // layer 3 fused: softmax stats + target gather (no logits store)
    gemm_kernel<3><<<dim3(8, ROWS / 128), 256, GEMM_SMEM_BYTES>>>(
        pH2, pW3, b3, nullptr, nullptr, tpos);

    finalize_kernel<<<BATCH, 256>>>(init, tpos, out);
}

// round 11
// speedup vs baseline: 1.0176x; 1.0176x over previous
#include <cuda_runtime.h>
#include <cuda_bf16.h>
#include <cstdint>

#define BATCH 2048
#define DIM   1024
#define HID   1024
#define STEPS 32
#define ROWS  (STEPS*BATCH)   /* 65536 */

// Output layout (float32, concatenated in reference return order)
#define OUT_FINAL   0
#define OUT_DELTA   (BATCH*DIM)                  /* 2097152 */
#define OUT_TLOG    (OUT_DELTA + STEPS*BATCH)    /* 2162688 */
#define OUT_VINIT   (OUT_TLOG + BATCH)           /* 2164736 */

// ---------------- device scratch (static globals: allocation-free) ----------
__device__ __align__(256) __nv_bfloat16 g_W1[DIM*HID];   // row-major [k][n]
__device__ __align__(256) __nv_bfloat16 g_W2[HID*HID];
__device__ __align__(256) __nv_bfloat16 g_W3[HID*DIM];
__device__ __align__(256) __nv_bfloat16 g_X0[(size_t)BATCH*DIM];
__device__ __align__(256) float         g_Z1[(size_t)BATCH*HID];
__device__ __align__(256) __nv_bfloat16 g_H1[(size_t)ROWS*HID];
__device__ __align__(256) __nv_bfloat16 g_H2[(size_t)ROWS*HID];
__device__ float g_sum[ROWS];    // per-row sum(exp(logit))
__device__ float g_tl [ROWS];    // per-row target logit

// ---------------- helpers -----------------------------------------------------
__device__ __forceinline__ uint32_t smem_u32(const void* p) {
    return (uint32_t)__cvta_generic_to_shared(p);
}
__device__ __forceinline__ void cp_async16(uint32_t s, const void* g) {
    asm volatile("cp.async.cg.shared.global [%0], [%1], 16;\n" :: "r"(s), "l"(g) : "memory");
}
__device__ __forceinline__ void cp_commit() {
    asm volatile("cp.async.commit_group;\n" ::: "memory");
}
template <int N>
__device__ __forceinline__ void cp_wait() {
    asm volatile("cp.async.wait_group %0;\n" :: "n"(N) : "memory");
}
__device__ __forceinline__ void ldsm_x4(uint32_t& r0, uint32_t& r1, uint32_t& r2,
                                        uint32_t& r3, uint32_t addr) {
    asm volatile("ldmatrix.sync.aligned.m8n8.x4.shared.b16 {%0,%1,%2,%3}, [%4];\n"
                 : "=r"(r0), "=r"(r1), "=r"(r2), "=r"(r3) : "r"(addr));
}
__device__ __forceinline__ void ldsm_x4_t(uint32_t& r0, uint32_t& r1, uint32_t& r2,
                                          uint32_t& r3, uint32_t addr) {
    asm volatile("ldmatrix.sync.aligned.m8n8.x4.trans.shared.b16 {%0,%1,%2,%3}, [%4];\n"
                 : "=r"(r0), "=r"(r1), "=r"(r2), "=r"(r3) : "r"(addr));
}
__device__ __forceinline__ void mma16816(float* c, const uint32_t* a, const uint32_t* b) {
    asm volatile("mma.sync.aligned.m16n8k16.row.col.f32.bf16.bf16.f32 "
                 "{%0,%1,%2,%3}, {%4,%5,%6,%7}, {%8,%9}, {%0,%1,%2,%3};\n"
                 : "+f"(c[0]), "+f"(c[1]), "+f"(c[2]), "+f"(c[3])
                 : "r"(a[0]), "r"(a[1]), "r"(a[2]), "r"(a[3]), "r"(b[0]), "r"(b[1]));
}

// ---------------- prep kernels --------------------------------------------------
__global__ void convert_weights_kernel(const float* __restrict__ W1,
                                       const float* __restrict__ W2,
                                       const float* __restrict__ W3) {
    int i = blockIdx.x * 256 + threadIdx.x;
    if (i < DIM * HID) {
        g_W1[i] = __float2bfloat16(W1[i]);
        g_W2[i] = __float2bfloat16(W2[i]);
        g_W3[i] = __float2bfloat16(W3[i]);
    }
}
__global__ void expand0_kernel(const float* __restrict__ init) {
    int i = blockIdx.x * 256 + threadIdx.x;
    if (i < BATCH * DIM) g_X0[i] = __float2bfloat16(init[i]);
}
// zero g_sum and emit delta output (both trivially parallel)
__global__ void prep_kernel(const int* __restrict__ tpos, float* __restrict__ out) {
    int i = blockIdx.x * 256 + threadIdx.x;
    if (i < ROWS) {
        g_sum[i] = 0.f;
        out[OUT_DELTA + i] = (float)tpos[i];
    }
}

// ---------------- the proven GEMM config (round-9): BM=BN=128 BK=64 -----------
// 256 threads (4 M-warps x 2 N-warps, 32x64 warp tile), 2 stages, 2 CTAs/SM.
// MODE 0: fp32 raw out (z1 base, no bias)
// MODE 2: bf16 relu(A@W + bias) out (layer 2)
// MODE 3: fused log-softmax stats (layer 3): g_sum[row] += sum(exp(logit));
//         g_tl[row] = logit[tpos[row]]. No logits store.
#define GEMM_SMEM_BYTES (2*128*72*2 + 2*64*136*2)   /* 71680 */

template <int MODE>
__global__ __launch_bounds__(256, 2)
void gemm_kernel(const __nv_bfloat16* __restrict__ A,
                 const __nv_bfloat16* __restrict__ W,
                 const float* __restrict__ bias,
                 __nv_bfloat16* __restrict__ outB,
                 float* __restrict__ outF,
                 const int* __restrict__ tpos) {
    constexpr int N = 1024, K = 1024, BM = 128, BK = 64, AP = 72, BP = 136;
    constexpr int NK = K / BK;
    extern __shared__ char smem_raw[];
    typedef __nv_bfloat16 bf;
    bf (*As)[BM][AP] = (bf(*)[BM][AP])smem_raw;
    bf (*Bs)[BK][BP] = (bf(*)[BK][BP])(smem_raw + 2 * BM * AP * sizeof(bf));
    __shared__ float sbias[128];
    __shared__ int stpos[128];

    const int rowBase = blockIdx.y * BM, colBase = blockIdx.x * 128;
    const int tid = threadIdx.x, lane = tid & 31, warp = tid >> 5;
    const int wm = (warp & 3) * 32, wn = (warp >> 2) * 64;
    const int lr = lane & 15, lc8 = (lane >> 4) << 3;

    if (MODE != 0 && tid < 128) sbias[tid] = bias[colBase + tid];
    if (MODE == 3 && tid < 128) stpos[tid] = tpos[rowBase + tid];

    float c[2][8][4];
#pragma unroll
    for (int i = 0; i < 2; i++)
#pragma unroll
        for (int j = 0; j < 8; j++)
#pragma unroll
            for (int k = 0; k < 4; k++) c[i][j][k] = 0.f;

    auto loadTiles = [&](int kt, int buf) {
#pragma unroll
        for (int i = 0; i < 4; i++) {
            int ch = tid + i * 256;
            int row = ch >> 3, kk = ch & 7;
            cp_async16(smem_u32(&As[buf][row][kk * 8]),
                       A + (size_t)(rowBase + row) * K + kt * BK + kk * 8);
            int br = ch >> 4, n8 = ch & 15;
            cp_async16(smem_u32(&Bs[buf][br][n8 * 8]),
                       W + (size_t)(kt * BK + br) * N + colBase + n8 * 8);
        }
    };
    loadTiles(0, 0);
    cp_commit();

    for (int kt = 0; kt < NK; ++kt) {
        cp_wait<0>();
        __syncthreads();
        if (kt + 1 < NK) { loadTiles(kt + 1, (kt + 1) & 1); cp_commit(); }
        const int buf = kt & 1;
#pragma unroll
        for (int kp = 0; kp < 4; kp++) {
            uint32_t a[2][4];
#pragma unroll
            for (int mi = 0; mi < 2; mi++)
                ldsm_x4(a[mi][0], a[mi][1], a[mi][2], a[mi][3],
                        smem_u32(&As[buf][wm + mi * 16 + lr][kp * 16 + lc8]));
            uint32_t b[8][2];
#pragma unroll
            for (int nj = 0; nj < 4; nj++) {
                uint32_t t0, t1, t2, t3;
                ldsm_x4_t(t0, t1, t2, t3,
                          smem_u32(&Bs[buf][kp * 16 + lr][wn + nj * 16 + lc8]));
                b[2 * nj][0] = t0; b[2 * nj][1] = t1;
                b[2 * nj + 1][0] = t2; b[2 * nj + 1][1] = t3;
            }
#pragma unroll
            for (int mi = 0; mi < 2; mi++)
#pragma unroll
                for (int ni = 0; ni < 8; ni++) mma16816(c[mi][ni], a[mi], b[ni]);
        }
    }

    if (MODE == 0) {
#pragma unroll
        for (int mi = 0; mi < 2; mi++)
#pragma unroll
            for (int ni = 0; ni < 8; ni++) {
                int col = colBase + wn + ni * 8 + (lane & 3) * 2;
                int r0 = rowBase + wm + mi * 16 + (lane >> 2);
                *(float2*)(outF + (size_t)r0 * N + col) =
                    make_float2(c[mi][ni][0], c[mi][ni][1]);
                *(float2*)(outF + (size_t)(r0 + 8) * N + col) =
                    make_float2(c[mi][ni][2], c[mi][ni][3]);
            }
    } else if (MODE == 2) {
#pragma unroll
        for (int mi = 0; mi < 2; mi++)
#pragma unroll
            for (int ni = 0; ni < 8; ni++) {
                int cl = wn + ni * 8 + (lane & 3) * 2;
                int col = colBase + cl;
                float bi0 = sbias[cl], bi1 = sbias[cl + 1];
                int r0 = rowBase + wm + mi * 16 + (lane >> 2);
                float x0 = fmaxf(c[mi][ni][0] + bi0, 0.f);
                float x1 = fmaxf(c[mi][ni][1] + bi1, 0.f);
                float x2 = fmaxf(c[mi][ni][2] + bi0, 0.f);
                float x3 = fmaxf(c[mi][ni][3] + bi1, 0.f);
                *(__nv_bfloat162*)(outB + (size_t)r0 * N + col) =
                    __floats2bfloat162_rn(x0, x1);
                *(__nv_bfloat162*)(outB + (size_t)(r0 + 8) * N + col) =
                    __floats2bfloat162_rn(x2, x3);
            }
    } else {
        // fused softmax stats: per-row sum of exp(logit) + target-logit gather.
        // logits are small (|z| < ~4): exp without max-subtraction is safe in fp32.
        float rsum[4];
#pragma unroll
        for (int i = 0; i < 4; i++) rsum[i] = 0.f;
#pragma unroll
        for (int mi = 0; mi < 2; mi++) {
            const int rA = rowBase + wm + mi * 16 + (lane >> 2);   // rows rA, rA+8
            const int pA = stpos[rA - rowBase];
            const int pB = stpos[rA + 8 - rowBase];
            const int cA = pA - colBase - wn;
            const int cB = pB - colBase - wn;
#pragma unroll
            for (int ni = 0; ni < 8; ni++) {
                int cl = wn + ni * 8 + (lane & 3) * 2;
                float bi0 = sbias[cl], bi1 = sbias[cl + 1];
                float x0 = c[mi][ni][0] + bi0, x1 = c[mi][ni][1] + bi1;
                float x2 = c[mi][ni][2] + bi0, x3 = c[mi][ni][3] + bi1;
                rsum[mi * 2]     += __expf(x0) + __expf(x1);
                rsum[mi * 2 + 1] += __expf(x2) + __expf(x3);
                // target gather: unique owner thread writes
                if ((cA >> 3) == ni && ((cA >> 1) & 3) == (lane & 3))
                    g_tl[rA] = (cA & 1) ? x1 : x0;
                if ((cB >> 3) == ni && ((cB >> 1) & 3) == (lane & 3))
                    g_tl[rA + 8] = (cB & 1) ? x3 : x2;
            }
        }
        // quad reduce (lanes sharing a row are lane^1, lane^2)
#pragma unroll
        for (int i = 0; i < 4; i++) {
            rsum[i] += __shfl_xor_sync(0xffffffffu, rsum[i], 1);
            rsum[i] += __shfl_xor_sync(0xffffffffu, rsum[i], 2);
        }
        if ((lane & 3) == 0) {
#pragma unroll
            for (int mi = 0; mi < 2; mi++) {
                int rA = rowBase + wm + mi * 16 + (lane >> 2);
                atomicAdd(&g_sum[rA], rsum[mi * 2]);
                atomicAdd(&g_sum[rA + 8], rsum[mi * 2 + 1]);
            }
        }
    }
}

// ---------------- incremental layer-1: H1 for all 32 steps (sync-free loop) ---
__global__ __launch_bounds__(256)
void h1_kernel(const float* __restrict__ init,
               const int* __restrict__ tpos,
               const float* __restrict__ b1) {
    const int b = blockIdx.x;
    const int tid = threadIdx.x;
    __shared__ unsigned char bits[DIM];
    __shared__ int   s_p[STEPS];
    __shared__ float s_sign[STEPS];

    float z[4], bb[4];
#pragma unroll
    for (int k = 0; k < 4; k++) {
        int col = tid + k * 256;
        z[k] = g_Z1[(size_t)b * HID + col];
        bb[k] = b1[col];
    }
    for (int i = tid; i < DIM; i += 256)
        bits[i] = (unsigned char)(init[(size_t)b * DIM + i] > 0.5f);
    __syncthreads();
    // precompute the full flip schedule once (tiny sequential pass)
    if (tid == 0) {
        for (int t = 0; t < STEPS; t++) {
            int p = tpos[t * BATCH + b];
            s_p[t] = p;
            s_sign[t] = 1.f - 2.f * (float)bits[p];
            bits[p] ^= 1;
        }
    }
    __syncthreads();
    // sync-free main loop: each thread owns its 4 z columns
    for (int t = 0; t < STEPS; t++) {
        const int row = t * BATCH + b;
        __nv_bfloat16* dst = g_H1 + (size_t)row * HID;
#pragma unroll
        for (int k = 0; k < 4; k++) {
            int col = tid + k * 256;
            dst[col] = __float2bfloat16(fmaxf(z[k] + bb[k], 0.f));
        }
        const int p = s_p[t];
        const float sg = s_sign[t];
        const __nv_bfloat16* wrow = g_W1 + (size_t)p * HID;
#pragma unroll
        for (int k = 0; k < 4; k++) {
            int col = tid + k * 256;
            z[k] += sg * __bfloat162float(wrow[col]);
        }
    }
}

// ---------------- assemble outputs --------------------------------------------
__global__ void finalize_kernel(const float* __restrict__ init,
                                const int* __restrict__ tpos,
                                float* __restrict__ out) {
    int b = blockIdx.x;
    const int tid = threadIdx.x;
    const float* src = init + (size_t)b * DIM;
    float* frow = out + OUT_FINAL + (size_t)b * DIM;
    float* vrow = out + OUT_VINIT + (size_t)b * DIM;
    for (int i = tid; i < DIM; i += blockDim.x) {
        float v = src[i];
        frow[i] = v;
        vrow[i] = v;
    }
    // parallel total_log: warp 0 handles the 32 steps, one per lane
    float part = 0.f;
    if (tid < 32) {
        int r = tid * BATCH + b;
        part = g_tl[r] - __logf(g_sum[r]);
#pragma unroll
        for (int o = 16; o; o >>= 1)
            part += __shfl_xor_sync(0xffffffffu, part, o);
    }
    __syncthreads();
    if (tid == 0) {
        for (int s = 0; s < STEPS; s++) {
            int p = tpos[s * BATCH + b];
            frow[p] = 1.0f - frow[p];
        }
        out[OUT_TLOG + b] = part;
    }
}

// ---------------- launch --------------------------------------------------------
extern "C" void kernel_launch(void* const* d_in, const int* in_sizes, int n_in,
                              void* d_out, int out_size) {
    const float* init = (const float*)d_in[0];
    const int*   tpos = (const int*)d_in[1];
    const float* W1   = (const float*)d_in[2];
    const float* b1   = (const float*)d_in[3];
    const float* W2   = (const float*)d_in[4];
    const float* b2   = (const float*)d_in[5];
    const float* W3   = (const float*)d_in[6];
    const float* b3   = (const float*)d_in[7];
    float* out = (float*)d_out;

    static __nv_bfloat16 *pW1 = nullptr, *pW2, *pW3, *pX0, *pH1, *pH2;
    static float *pZ1;
    if (!pW1) {
        cudaGetSymbolAddress((void**)&pW1, g_W1);
        cudaGetSymbolAddress((void**)&pW2, g_W2);
        cudaGetSymbolAddress((void**)&pW3, g_W3);
        cudaGetSymbolAddress((void**)&pX0, g_X0);
        cudaGetSymbolAddress((void**)&pH1, g_H1);
        cudaGetSymbolAddress((void**)&pH2, g_H2);
        cudaGetSymbolAddress((void**)&pZ1, g_Z1);
        cudaFuncSetAttribute(gemm_kernel<0>,
            cudaFuncAttributeMaxDynamicSharedMemorySize, GEMM_SMEM_BYTES);
        cudaFuncSetAttribute(gemm_kernel<2>,
            cudaFuncAttributeMaxDynamicSharedMemorySize, GEMM_SMEM_BYTES);
        cudaFuncSetAttribute(gemm_kernel<3>,
            cudaFuncAttributeMaxDynamicSharedMemorySize, GEMM_SMEM_BYTES);
    }

    convert_weights_kernel<<<(DIM * HID + 255) / 256, 256>>>(W1, W2, W3);
    expand0_kernel<<<(BATCH * DIM + 255) / 256, 256>>>(init);
    prep_kernel<<<(ROWS + 255) / 256, 256>>>(tpos, out);

    // z1_base = X0 @ W1 (fp32 raw)
    gemm_kernel<0><<<dim3(8, BATCH / 128), 256, GEMM_SMEM_BYTES>>>(
        pX0, pW1, nullptr, nullptr, pZ1, nullptr);
    // incremental layer 1
    h1_kernel<<<BATCH, 256>>>(init, tpos, b1);
    // layer 2: H2 = relu(H1 @ W2 + b2)
    gemm_kernel<2><<<dim3(8, ROWS / 128), 256, GEMM_SMEM_BYTES>>>(
        pH1, pW2, b2, pH2, nullptr, nullptr);
    // layer 3 fused: softmax stats + target gather (no logits store)
    gemm_kernel<3><<<dim3(8, ROWS / 128), 256, GEMM_SMEM_BYTES>>>(
        pH2, pW3, b3, nullptr, nullptr, tpos);

    finalize_kernel<<<BATCH, 256>>>(init, tpos, out);
}

// round 12
// speedup vs baseline: 1.0297x; 1.0119x over previous
#include <cuda_runtime.h>
#include <cuda_bf16.h>
#include <cstdint>

#define BATCH 2048
#define DIM   1024
#define HID   1024
#define STEPS 32
#define ROWS  (STEPS*BATCH)   /* 65536 */

// Output layout (float32, concatenated in reference return order)
#define OUT_FINAL   0
#define OUT_DELTA   (BATCH*DIM)                  /* 2097152 */
#define OUT_TLOG    (OUT_DELTA + STEPS*BATCH)    /* 2162688 */
#define OUT_VINIT   (OUT_TLOG + BATCH)           /* 2164736 */

// ---------------- device scratch (static globals: allocation-free) ----------
__device__ __align__(256) __nv_bfloat16 g_W1[DIM*HID];   // row-major [k][n]
__device__ __align__(256) __nv_bfloat16 g_W2[HID*HID];
__device__ __align__(256) __nv_bfloat16 g_W3[HID*DIM];
__device__ __align__(256) __nv_bfloat16 g_X0[(size_t)BATCH*DIM];
__device__ __align__(256) float         g_Z1[(size_t)BATCH*HID];
__device__ __align__(256) __nv_bfloat16 g_H1[(size_t)ROWS*HID];
__device__ __align__(256) __nv_bfloat16 g_H2[(size_t)ROWS*HID];
__device__ float g_sum[ROWS];    // per-row sum(exp(logit))
__device__ float g_tl [ROWS];    // per-row target logit

// ---------------- helpers -----------------------------------------------------
__device__ __forceinline__ uint32_t smem_u32(const void* p) {
    return (uint32_t)__cvta_generic_to_shared(p);
}
__device__ __forceinline__ void cp_async16(uint32_t s, const void* g) {
    asm volatile("cp.async.cg.shared.global [%0], [%1], 16;\n" :: "r"(s), "l"(g) : "memory");
}
__device__ __forceinline__ void cp_commit() {
    asm volatile("cp.async.commit_group;\n" ::: "memory");
}
template <int N>
__device__ __forceinline__ void cp_wait() {
    asm volatile("cp.async.wait_group %0;\n" :: "n"(N) : "memory");
}
__device__ __forceinline__ void ldsm_x4(uint32_t& r0, uint32_t& r1, uint32_t& r2,
                                        uint32_t& r3, uint32_t addr) {
    asm volatile("ldmatrix.sync.aligned.m8n8.x4.shared.b16 {%0,%1,%2,%3}, [%4];\n"
                 : "=r"(r0), "=r"(r1), "=r"(r2), "=r"(r3) : "r"(addr));
}
__device__ __forceinline__ void ldsm_x4_t(uint32_t& r0, uint32_t& r1, uint32_t& r2,
                                          uint32_t& r3, uint32_t addr) {
    asm volatile("ldmatrix.sync.aligned.m8n8.x4.trans.shared.b16 {%0,%1,%2,%3}, [%4];\n"
                 : "=r"(r0), "=r"(r1), "=r"(r2), "=r"(r3) : "r"(addr));
}
__device__ __forceinline__ void mma16816(float* c, const uint32_t* a, const uint32_t* b) {
    asm volatile("mma.sync.aligned.m16n8k16.row.col.f32.bf16.bf16.f32 "
                 "{%0,%1,%2,%3}, {%4,%5,%6,%7}, {%8,%9}, {%0,%1,%2,%3};\n"
                 : "+f"(c[0]), "+f"(c[1]), "+f"(c[2]), "+f"(c[3])
                 : "r"(a[0]), "r"(a[1]), "r"(a[2]), "r"(a[3]), "r"(b[0]), "r"(b[1]));
}

// ---------------- merged prep: weights->bf16, X0, g_sum zero, delta out -------
__global__ void prep_all_kernel(const float* __restrict__ W1,
                                const float* __restrict__ W2,
                                const float* __restrict__ W3,
                                const float* __restrict__ init,
                                const int* __restrict__ tpos,
                                float* __restrict__ out) {
    int i = blockIdx.x * 256 + threadIdx.x;
    if (i < DIM * HID) {
        g_W1[i] = __float2bfloat16(W1[i]);
        g_W2[i] = __float2bfloat16(W2[i]);
        g_W3[i] = __float2bfloat16(W3[i]);
    }
    if (i < BATCH * DIM) g_X0[i] = __float2bfloat16(init[i]);
    if (i < ROWS) {
        g_sum[i] = 0.f;
        out[OUT_DELTA + i] = (float)tpos[i];
    }
}

// ---------------- the proven GEMM config: BM=BN=128 BK=64, 2 stages -----------
// 256 threads (4 M-warps x 2 N-warps, 32x64 warp tile), 2 CTAs/SM.
// MODE 0: fp32 raw out (z1 base, no bias)
// MODE 2: bf16 relu(A@W + bias) out (layer 2)
// MODE 3: fused log-softmax stats (layer 3): g_sum[row] += sum(exp(logit));
//         g_tl[row] = logit[tpos[row]]. No logits store.
#define GEMM_SMEM_BYTES (2*128*72*2 + 2*64*136*2)   /* 71680 */

template <int MODE>
__global__ __launch_bounds__(256, 2)
void gemm_kernel(const __nv_bfloat16* __restrict__ A,
                 const __nv_bfloat16* __restrict__ W,
                 const float* __restrict__ bias,
                 __nv_bfloat16* __restrict__ outB,
                 float* __restrict__ outF,
                 const int* __restrict__ tpos) {
    constexpr int N = 1024, K = 1024, BM = 128, BK = 64, AP = 72, BP = 136;
    constexpr int NK = K / BK;
    extern __shared__ char smem_raw[];
    typedef __nv_bfloat16 bf;
    bf (*As)[BM][AP] = (bf(*)[BM][AP])smem_raw;
    bf (*Bs)[BK][BP] = (bf(*)[BK][BP])(smem_raw + 2 * BM * AP * sizeof(bf));
    __shared__ float sbias[128];
    __shared__ int stpos[128];

    const int rowBase = blockIdx.y * BM, colBase = blockIdx.x * 128;
    const int tid = threadIdx.x, lane = tid & 31, warp = tid >> 5;
    const int wm = (warp & 3) * 32, wn = (warp >> 2) * 64;
    const int lr = lane & 15, lc8 = (lane >> 4) << 3;

    if (MODE != 0 && tid < 128) sbias[tid] = bias[colBase + tid];
    if (MODE == 3 && tid < 128) stpos[tid] = tpos[rowBase + tid];

    float c[2][8][4];
#pragma unroll
    for (int i = 0; i < 2; i++)
#pragma unroll
        for (int j = 0; j < 8; j++)
#pragma unroll
            for (int k = 0; k < 4; k++) c[i][j][k] = 0.f;

    auto loadTiles = [&](int kt, int buf) {
#pragma unroll
        for (int i = 0; i < 4; i++) {
            int ch = tid + i * 256;
            int row = ch >> 3, kk = ch & 7;
            cp_async16(smem_u32(&As[buf][row][kk * 8]),
                       A + (size_t)(rowBase + row) * K + kt * BK + kk * 8);
            int br = ch >> 4, n8 = ch & 15;
            cp_async16(smem_u32(&Bs[buf][br][n8 * 8]),
                       W + (size_t)(kt * BK + br) * N + colBase + n8 * 8);
        }
    };
    loadTiles(0, 0);
    cp_commit();

    for (int kt = 0; kt < NK; ++kt) {
        cp_wait<0>();
        __syncthreads();
        if (kt + 1 < NK) { loadTiles(kt + 1, (kt + 1) & 1); cp_commit(); }
        const int buf = kt & 1;
#pragma unroll
        for (int kp = 0; kp < 4; kp++) {
            uint32_t a[2][4];
#pragma unroll
            for (int mi = 0; mi < 2; mi++)
                ldsm_x4(a[mi][0], a[mi][1], a[mi][2], a[mi][3],
                        smem_u32(&As[buf][wm + mi * 16 + lr][kp * 16 + lc8]));
            uint32_t b[8][2];
#pragma unroll
            for (int nj = 0; nj < 4; nj++) {
                uint32_t t0, t1, t2, t3;
                ldsm_x4_t(t0, t1, t2, t3,
                          smem_u32(&Bs[buf][kp * 16 + lr][wn + nj * 16 + lc8]));
                b[2 * nj][0] = t0; b[2 * nj][1] = t1;
                b[2 * nj + 1][0] = t2; b[2 * nj + 1][1] = t3;
            }
#pragma unroll
            for (int mi = 0; mi < 2; mi++)
#pragma unroll
                for (int ni = 0; ni < 8; ni++) mma16816(c[mi][ni], a[mi], b[ni]);
        }
    }

    if (MODE == 0) {
#pragma unroll
        for (int mi = 0; mi < 2; mi++)
#pragma unroll
            for (int ni = 0; ni < 8; ni++) {
                int col = colBase + wn + ni * 8 + (lane & 3) * 2;
                int r0 = rowBase + wm + mi * 16 + (lane >> 2);
                *(float2*)(outF + (size_t)r0 * N + col) =
                    make_float2(c[mi][ni][0], c[mi][ni][1]);
                *(float2*)(outF + (size_t)(r0 + 8) * N + col) =
                    make_float2(c[mi][ni][2], c[mi][ni][3]);
            }
    } else if (MODE == 2) {
#pragma unroll
        for (int mi = 0; mi < 2; mi++)
#pragma unroll
            for (int ni = 0; ni < 8; ni++) {
                int cl = wn + ni * 8 + (lane & 3) * 2;
                int col = colBase + cl;
                float bi0 = sbias[cl], bi1 = sbias[cl + 1];
                int r0 = rowBase + wm + mi * 16 + (lane >> 2);
                float x0 = fmaxf(c[mi][ni][0] + bi0, 0.f);
                float x1 = fmaxf(c[mi][ni][1] + bi1, 0.f);
                float x2 = fmaxf(c[mi][ni][2] + bi0, 0.f);
                float x3 = fmaxf(c[mi][ni][3] + bi1, 0.f);
                *(__nv_bfloat162*)(outB + (size_t)r0 * N + col) =
                    __floats2bfloat162_rn(x0, x1);
                *(__nv_bfloat162*)(outB + (size_t)(r0 + 8) * N + col) =
                    __floats2bfloat162_rn(x2, x3);
            }
    } else {
        // fused softmax stats: per-row sum of exp(logit) + target-logit gather.
        // logits are small (|z| < ~4): exp without max-subtraction is safe in fp32.
        float rsum[4];
#pragma unroll
        for (int i = 0; i < 4; i++) rsum[i] = 0.f;
#pragma unroll
        for (int mi = 0; mi < 2; mi++) {
            const int rA = rowBase + wm + mi * 16 + (lane >> 2);   // rows rA, rA+8
            const int pA = stpos[rA - rowBase];
            const int pB = stpos[rA + 8 - rowBase];
            const int cA = pA - colBase - wn;
            const int cB = pB - colBase - wn;
#pragma unroll
            for (int ni = 0; ni < 8; ni++) {
                int cl = wn + ni * 8 + (lane & 3) * 2;
                float bi0 = sbias[cl], bi1 = sbias[cl + 1];
                float x0 = c[mi][ni][0] + bi0, x1 = c[mi][ni][1] + bi1;
                float x2 = c[mi][ni][2] + bi0, x3 = c[mi][ni][3] + bi1;
                rsum[mi * 2]     += __expf(x0) + __expf(x1);
                rsum[mi * 2 + 1] += __expf(x2) + __expf(x3);
                // target gather: unique owner thread writes
                if ((cA >> 3) == ni && ((cA >> 1) & 3) == (lane & 3))
                    g_tl[rA] = (cA & 1) ? x1 : x0;
                if ((cB >> 3) == ni && ((cB >> 1) & 3) == (lane & 3))
                    g_tl[rA + 8] = (cB & 1) ? x3 : x2;
            }
        }
        // quad reduce (lanes sharing a row are lane^1, lane^2)
#pragma unroll
        for (int i = 0; i < 4; i++) {
            rsum[i] += __shfl_xor_sync(0xffffffffu, rsum[i], 1);
            rsum[i] += __shfl_xor_sync(0xffffffffu, rsum[i], 2);
        }
        if ((lane & 3) == 0) {
#pragma unroll
            for (int mi = 0; mi < 2; mi++) {
                int rA = rowBase + wm + mi * 16 + (lane >> 2);
                atomicAdd(&g_sum[rA], rsum[mi * 2]);
                atomicAdd(&g_sum[rA + 8], rsum[mi * 2 + 1]);
            }
        }
    }
}

// ---------------- incremental layer-1: sync-free loop + W-row prefetch --------
__global__ __launch_bounds__(256)
void h1_kernel(const float* __restrict__ init,
               const int* __restrict__ tpos,
               const float* __restrict__ b1) {
    const int b = blockIdx.x;
    const int tid = threadIdx.x;
    __shared__ unsigned char bits[DIM];
    __shared__ int   s_p[STEPS];
    __shared__ float s_sign[STEPS];

    float z[4], bb[4];
#pragma unroll
    for (int k = 0; k < 4; k++) {
        int col = tid + k * 256;
        z[k] = g_Z1[(size_t)b * HID + col];
        bb[k] = b1[col];
    }
    for (int i = tid; i < DIM; i += 256)
        bits[i] = (unsigned char)(init[(size_t)b * DIM + i] > 0.5f);
    __syncthreads();
    // precompute the full flip schedule once (tiny sequential pass)
    if (tid == 0) {
        for (int t = 0; t < STEPS; t++) {
            int p = tpos[t * BATCH + b];
            s_p[t] = p;
            s_sign[t] = 1.f - 2.f * (float)bits[p];
            bits[p] ^= 1;
        }
    }
    __syncthreads();

    // prefetch W1 row for step 0
    __nv_bfloat16 wv[4];
    {
        const __nv_bfloat16* wrow = g_W1 + (size_t)s_p[0] * HID;
#pragma unroll
        for (int k = 0; k < 4; k++) wv[k] = wrow[tid + k * 256];
    }

    // sync-free main loop; issue next row's loads before consuming this row's
    for (int t = 0; t < STEPS; t++) {
        const int row = t * BATCH + b;
        __nv_bfloat16* dst = g_H1 + (size_t)row * HID;
#pragma unroll
        for (int k = 0; k < 4; k++) {
            int col = tid + k * 256;
            dst[col] = __float2bfloat16(fmaxf(z[k] + bb[k], 0.f));
        }
        const float sg = s_sign[t];
        float wf[4];
#pragma unroll
        for (int k = 0; k < 4; k++) wf[k] = __bfloat162float(wv[k]);
        if (t + 1 < STEPS) {
            const __nv_bfloat16* wnext = g_W1 + (size_t)s_p[t + 1] * HID;
#pragma unroll
            for (int k = 0; k < 4; k++) wv[k] = wnext[tid + k * 256];
        }
#pragma unroll
        for (int k = 0; k < 4; k++) z[k] += sg * wf[k];
    }
}

// ---------------- assemble outputs --------------------------------------------
__global__ void finalize_kernel(const float* __restrict__ init,
                                const int* __restrict__ tpos,
                                float* __restrict__ out) {
    int b = blockIdx.x;
    const int tid = threadIdx.x;
    const float* src = init + (size_t)b * DIM;
    float* frow = out + OUT_FINAL + (size_t)b * DIM;
    float* vrow = out + OUT_VINIT + (size_t)b * DIM;
    for (int i = tid; i < DIM; i += blockDim.x) {
        float v = src[i];
        frow[i] = v;
        vrow[i] = v;
    }
    // parallel total_log: warp 0 handles the 32 steps, one per lane
    float part = 0.f;
    if (tid < 32) {
        int r = tid * BATCH + b;
        part = g_tl[r] - __logf(g_sum[r]);
#pragma unroll
        for (int o = 16; o; o >>= 1)
            part += __shfl_xor_sync(0xffffffffu, part, o);
    }
    __syncthreads();
    if (tid == 0) {
        for (int s = 0; s < STEPS; s++) {
            int p = tpos[s * BATCH + b];
            frow[p] = 1.0f - frow[p];
        }
        out[OUT_TLOG + b] = part;
    }
}

// ---------------- launch --------------------------------------------------------
extern "C" void kernel_launch(void* const* d_in, const int* in_sizes, int n_in,
                              void* d_out, int out_size) {
    const float* init = (const float*)d_in[0];
    const int*   tpos = (const int*)d_in[1];
    const float* W1   = (const float*)d_in[2];
    const float* b1   = (const float*)d_in[3];
    const float* W2   = (const float*)d_in[4];
    const float* b2   = (const float*)d_in[5];
    const float* W3   = (const float*)d_in[6];
    const float* b3   = (const float*)d_in[7];
    float* out = (float*)d_out;

    static __nv_bfloat16 *pW1 = nullptr, *pW2, *pW3, *pX0, *pH1, *pH2;
    static float *pZ1;
    if (!pW1) {
        cudaGetSymbolAddress((void**)&pW1, g_W1);
        cudaGetSymbolAddress((void**)&pW2, g_W2);
        cudaGetSymbolAddress((void**)&pW3, g_W3);
        cudaGetSymbolAddress((void**)&pX0, g_X0);
        cudaGetSymbolAddress((void**)&pH1, g_H1);
        cudaGetSymbolAddress((void**)&pH2, g_H2);
        cudaGetSymbolAddress((void**)&pZ1, g_Z1);
        cudaFuncSetAttribute(gemm_kernel<0>,
            cudaFuncAttributeMaxDynamicSharedMemorySize, GEMM_SMEM_BYTES);
        cudaFuncSetAttribute(gemm_kernel<2>,
            cudaFuncAttributeMaxDynamicSharedMemorySize, GEMM_SMEM_BYTES);
        cudaFuncSetAttribute(gemm_kernel<3>,
            cudaFuncAttributeMaxDynamicSharedMemorySize, GEMM_SMEM_BYTES);
    }

    // merged prep (weights, X0, sum zeroing, delta output) in one launch
    prep_all_kernel<<<(BATCH * DIM + 255) / 256, 256>>>(W1, W2, W3, init, tpos, out);

    // z1_base = X0 @ W1 (fp32 raw)
    gemm_kernel<0><<<dim3(8, BATCH / 128), 256, GEMM_SMEM_BYTES>>>(
        pX0, pW1, nullptr, nullptr, pZ1, nullptr);
    // incremental layer 1
    h1_kernel<<<BATCH, 256>>>(init, tpos, b1);
    // layer 2: H2 = relu(H1 @ W2 + b2)
    gemm_kernel<2><<<dim3(8, ROWS / 128), 256, GEMM_SMEM_BYTES>>>(
        pH1, pW2, b2, pH2, nullptr, nullptr);
    // layer 3 fused: softmax stats + target gather (no logits store)
    gemm_kernel<3><<<dim3(8, ROWS / 128), 256, GEMM_SMEM_BYTES>>>(
        pH2, pW3, b3, nullptr, nullptr, tpos);

    finalize_kernel<<<BATCH, 256>>>(init, tpos, out);
}

// round 14
// speedup vs baseline: 1.0328x; 1.0030x over previous
#include <cuda_runtime.h>
#include <cuda_bf16.h>
#include <cstdint>

#define BATCH 2048
#define DIM   1024
#define HID   1024
#define STEPS 32
#define ROWS  (STEPS*BATCH)   /* 65536 */

// Output layout (float32, concatenated in reference return order)
#define OUT_FINAL   0
#define OUT_DELTA   (BATCH*DIM)                  /* 2097152 */
#define OUT_TLOG    (OUT_DELTA + STEPS*BATCH)    /* 2162688 */
#define OUT_VINIT   (OUT_TLOG + BATCH)           /* 2164736 */

// ---------------- device scratch (static globals: allocation-free) ----------
__device__ __align__(256) __nv_bfloat16 g_W1[DIM*HID];   // row-major [k][n]
__device__ __align__(256) __nv_bfloat16 g_W2[HID*HID];
__device__ __align__(256) __nv_bfloat16 g_W3[HID*DIM];
__device__ __align__(256) __nv_bfloat16 g_X0[(size_t)BATCH*DIM];
__device__ __align__(256) float         g_Z1[(size_t)BATCH*HID];
__device__ __align__(256) __nv_bfloat16 g_H1[(size_t)ROWS*HID];
__device__ __align__(256) __nv_bfloat16 g_H2[(size_t)ROWS*HID];
__device__ float g_sum[ROWS];    // per-row sum(exp(logit))
__device__ float g_tl [ROWS];    // per-row target logit

// ---------------- helpers -----------------------------------------------------
__device__ __forceinline__ uint32_t smem_u32(const void* p) {
    return (uint32_t)__cvta_generic_to_shared(p);
}
__device__ __forceinline__ void cp_async16(uint32_t s, const void* g) {
    asm volatile("cp.async.cg.shared.global [%0], [%1], 16;\n" :: "r"(s), "l"(g) : "memory");
}
__device__ __forceinline__ void cp_commit() {
    asm volatile("cp.async.commit_group;\n" ::: "memory");
}
template <int N>
__device__ __forceinline__ void cp_wait() {
    asm volatile("cp.async.wait_group %0;\n" :: "n"(N) : "memory");
}
__device__ __forceinline__ void ldsm_x4(uint32_t& r0, uint32_t& r1, uint32_t& r2,
                                        uint32_t& r3, uint32_t addr) {
    asm volatile("ldmatrix.sync.aligned.m8n8.x4.shared.b16 {%0,%1,%2,%3}, [%4];\n"
                 : "=r"(r0), "=r"(r1), "=r"(r2), "=r"(r3) : "r"(addr));
}
__device__ __forceinline__ void ldsm_x4_t(uint32_t& r0, uint32_t& r1, uint32_t& r2,
                                          uint32_t& r3, uint32_t addr) {
    asm volatile("ldmatrix.sync.aligned.m8n8.x4.trans.shared.b16 {%0,%1,%2,%3}, [%4];\n"
                 : "=r"(r0), "=r"(r1), "=r"(r2), "=r"(r3) : "r"(addr));
}
__device__ __forceinline__ void mma16816(float* c, const uint32_t* a, const uint32_t* b) {
    asm volatile("mma.sync.aligned.m16n8k16.row.col.f32.bf16.bf16.f32 "
                 "{%0,%1,%2,%3}, {%4,%5,%6,%7}, {%8,%9}, {%0,%1,%2,%3};\n"
                 : "+f"(c[0]), "+f"(c[1]), "+f"(c[2]), "+f"(c[3])
                 : "r"(a[0]), "r"(a[1]), "r"(a[2]), "r"(a[3]), "r"(b[0]), "r"(b[1]));
}
// pack float4 -> 4 bf16 (8 bytes)
__device__ __forceinline__ uint2 bf16x4_pack(float4 v) {
    union { uint2 u; __nv_bfloat162 h[2]; } r;
    r.h[0] = __floats2bfloat162_rn(v.x, v.y);
    r.h[1] = __floats2bfloat162_rn(v.z, v.w);
    return r.u;
}

// ---------------- merged + vectorized prep -------------------------------------
// grid: 2048 blocks x 256 thr (covers X0's 2M elems at 4/thread).
// First 1M elems also convert W1/W2/W3; first 64K do sum-zero + delta out.
__global__ void prep_all_kernel(const float* __restrict__ W1,
                                const float* __restrict__ W2,
                                const float* __restrict__ W3,
                                const float* __restrict__ init,
                                const int* __restrict__ tpos,
                                float* __restrict__ out) {
    int c = blockIdx.x * 256 + threadIdx.x;       // chunk id (4 elems)
    int i = c * 4;
    if (i < DIM * HID) {
        *(uint2*)(g_W1 + i) = bf16x4_pack(*(const float4*)(W1 + i));
        *(uint2*)(g_W2 + i) = bf16x4_pack(*(const float4*)(W2 + i));
        *(uint2*)(g_W3 + i) = bf16x4_pack(*(const float4*)(W3 + i));
    }
    if (i < BATCH * DIM)
        *(uint2*)(g_X0 + i) = bf16x4_pack(*(const float4*)(init + i));
    if (i < ROWS) {
        *(float4*)(g_sum + i) = make_float4(0.f, 0.f, 0.f, 0.f);
        int4 t = *(const int4*)(tpos + i);
        *(float4*)(out + OUT_DELTA + i) =
            make_float4((float)t.x, (float)t.y, (float)t.z, (float)t.w);
    }
}

// ---------------- the proven GEMM config: BM=BN=128 BK=64, 2 stages -----------
// 256 threads (4 M-warps x 2 N-warps, 32x64 warp tile), 2 CTAs/SM.
// MODE 0: fp32 raw out (z1 base, no bias)
// MODE 2: bf16 relu(A@W + bias) out (layer 2)
// MODE 3: fused log-softmax stats (layer 3): g_sum[row] += sum(exp(logit));
//         g_tl[row] = logit[tpos[row]]. No logits store.
#define GEMM_SMEM_BYTES (2*128*72*2 + 2*64*136*2)   /* 71680 */

template <int MODE>
__global__ __launch_bounds__(256, 2)
void gemm_kernel(const __nv_bfloat16* __restrict__ A,
                 const __nv_bfloat16* __restrict__ W,
                 const float* __restrict__ bias,
                 __nv_bfloat16* __restrict__ outB,
                 float* __restrict__ outF,
                 const int* __restrict__ tpos) {
    constexpr int N = 1024, K = 1024, BM = 128, BK = 64, AP = 72, BP = 136;
    constexpr int NK = K / BK;
    extern __shared__ char smem_raw[];
    typedef __nv_bfloat16 bf;
    bf (*As)[BM][AP] = (bf(*)[BM][AP])smem_raw;
    bf (*Bs)[BK][BP] = (bf(*)[BK][BP])(smem_raw + 2 * BM * AP * sizeof(bf));
    __shared__ float sbias[128];
    __shared__ int stpos[128];

    const int rowBase = blockIdx.y * BM, colBase = blockIdx.x * 128;
    const int tid = threadIdx.x, lane = tid & 31, warp = tid >> 5;
    const int wm = (warp & 3) * 32, wn = (warp >> 2) * 64;
    const int lr = lane & 15, lc8 = (lane >> 4) << 3;

    if (MODE != 0 && tid < 128) sbias[tid] = bias[colBase + tid];
    if (MODE == 3 && tid < 128) stpos[tid] = tpos[rowBase + tid];

    float c[2][8][4];
#pragma unroll
    for (int i = 0; i < 2; i++)
#pragma unroll
        for (int j = 0; j < 8; j++)
#pragma unroll
            for (int k = 0; k < 4; k++) c[i][j][k] = 0.f;

    auto loadTiles = [&](int kt, int buf) {
#pragma unroll
        for (int i = 0; i < 4; i++) {
            int ch = tid + i * 256;
            int row = ch >> 3, kk = ch & 7;
            cp_async16(smem_u32(&As[buf][row][kk * 8]),
                       A + (size_t)(rowBase + row) * K + kt * BK + kk * 8);
            int br = ch >> 4, n8 = ch & 15;
            cp_async16(smem_u32(&Bs[buf][br][n8 * 8]),
                       W + (size_t)(kt * BK + br) * N + colBase + n8 * 8);
        }
    };
    loadTiles(0, 0);
    cp_commit();

    for (int kt = 0; kt < NK; ++kt) {
        cp_wait<0>();
        __syncthreads();
        if (kt + 1 < NK) { loadTiles(kt + 1, (kt + 1) & 1); cp_commit(); }
        const int buf = kt & 1;
#pragma unroll
        for (int kp = 0; kp < 4; kp++) {
            uint32_t a[2][4];
#pragma unroll
            for (int mi = 0; mi < 2; mi++)
                ldsm_x4(a[mi][0], a[mi][1], a[mi][2], a[mi][3],
                        smem_u32(&As[buf][wm + mi * 16 + lr][kp * 16 + lc8]));
            uint32_t b[8][2];
#pragma unroll
            for (int nj = 0; nj < 4; nj++) {
                uint32_t t0, t1, t2, t3;
                ldsm_x4_t(t0, t1, t2, t3,
                          smem_u32(&Bs[buf][kp * 16 + lr][wn + nj * 16 + lc8]));
                b[2 * nj][0] = t0; b[2 * nj][1] = t1;
                b[2 * nj + 1][0] = t2; b[2 * nj + 1][1] = t3;
            }
#pragma unroll
            for (int mi = 0; mi < 2; mi++)
#pragma unroll
                for (int ni = 0; ni < 8; ni++) mma16816(c[mi][ni], a[mi], b[ni]);
        }
    }

    if (MODE == 0) {
#pragma unroll
        for (int mi = 0; mi < 2; mi++)
#pragma unroll
            for (int ni = 0; ni < 8; ni++) {
                int col = colBase + wn + ni * 8 + (lane & 3) * 2;
                int r0 = rowBase + wm + mi * 16 + (lane >> 2);
                *(float2*)(outF + (size_t)r0 * N + col) =
                    make_float2(c[mi][ni][0], c[mi][ni][1]);
                *(float2*)(outF + (size_t)(r0 + 8) * N + col) =
                    make_float2(c[mi][ni][2], c[mi][ni][3]);
            }
    } else if (MODE == 2) {
#pragma unroll
        for (int mi = 0; mi < 2; mi++)
#pragma unroll
            for (int ni = 0; ni < 8; ni++) {
                int cl = wn + ni * 8 + (lane & 3) * 2;
                int col = colBase + cl;
                float bi0 = sbias[cl], bi1 = sbias[cl + 1];
                int r0 = rowBase + wm + mi * 16 + (lane >> 2);
                float x0 = fmaxf(c[mi][ni][0] + bi0, 0.f);
                float x1 = fmaxf(c[mi][ni][1] + bi1, 0.f);
                float x2 = fmaxf(c[mi][ni][2] + bi0, 0.f);
                float x3 = fmaxf(c[mi][ni][3] + bi1, 0.f);
                *(__nv_bfloat162*)(outB + (size_t)r0 * N + col) =
                    __floats2bfloat162_rn(x0, x1);
                *(__nv_bfloat162*)(outB + (size_t)(r0 + 8) * N + col) =
                    __floats2bfloat162_rn(x2, x3);
            }
    } else {
        // fused softmax stats: per-row sum of exp(logit) + target-logit gather.
        // logits are small (|z| < ~4): exp without max-subtraction is safe in fp32.
        float rsum[4];
#pragma unroll
        for (int i = 0; i < 4; i++) rsum[i] = 0.f;
#pragma unroll
        for (int mi = 0; mi < 2; mi++) {
            const int rA = rowBase + wm + mi * 16 + (lane >> 2);   // rows rA, rA+8
            const int pA = stpos[rA - rowBase];
            const int pB = stpos[rA + 8 - rowBase];
            const int cA = pA - colBase - wn;
            const int cB = pB - colBase - wn;
#pragma unroll
            for (int ni = 0; ni < 8; ni++) {
                int cl = wn + ni * 8 + (lane & 3) * 2;
                float bi0 = sbias[cl], bi1 = sbias[cl + 1];
                float x0 = c[mi][ni][0] + bi0, x1 = c[mi][ni][1] + bi1;
                float x2 = c[mi][ni][2] + bi0, x3 = c[mi][ni][3] + bi1;
                rsum[mi * 2]     += __expf(x0) + __expf(x1);
                rsum[mi * 2 + 1] += __expf(x2) + __expf(x3);
                // target gather: unique owner thread writes
                if ((cA >> 3) == ni && ((cA >> 1) & 3) == (lane & 3))
                    g_tl[rA] = (cA & 1) ? x1 : x0;
                if ((cB >> 3) == ni && ((cB >> 1) & 3) == (lane & 3))
                    g_tl[rA + 8] = (cB & 1) ? x3 : x2;
            }
        }
        // quad reduce (lanes sharing a row are lane^1, lane^2)
#pragma unroll
        for (int i = 0; i < 4; i++) {
            rsum[i] += __shfl_xor_sync(0xffffffffu, rsum[i], 1);
            rsum[i] += __shfl_xor_sync(0xffffffffu, rsum[i], 2);
        }
        if ((lane & 3) == 0) {
#pragma unroll
            for (int mi = 0; mi < 2; mi++) {
                int rA = rowBase + wm + mi * 16 + (lane >> 2);
                atomicAdd(&g_sum[rA], rsum[mi * 2]);
                atomicAdd(&g_sum[rA + 8], rsum[mi * 2 + 1]);
            }
        }
    }
}

// ---------------- incremental layer-1: sync-free loop + W-row prefetch --------
__global__ __launch_bounds__(256)
void h1_kernel(const float* __restrict__ init,
               const int* __restrict__ tpos,
               const float* __restrict__ b1) {
    const int b = blockIdx.x;
    const int tid = threadIdx.x;
    __shared__ unsigned char bits[DIM];
    __shared__ int   s_p[STEPS];
    __shared__ float s_sign[STEPS];

    float z[4], bb[4];
#pragma unroll
    for (int k = 0; k < 4; k++) {
        int col = tid + k * 256;
        z[k] = g_Z1[(size_t)b * HID + col];
        bb[k] = b1[col];
    }
    for (int i = tid; i < DIM; i += 256)
        bits[i] = (unsigned char)(init[(size_t)b * DIM + i] > 0.5f);
    __syncthreads();
    // precompute the full flip schedule once (tiny sequential pass)
    if (tid == 0) {
        for (int t = 0; t < STEPS; t++) {
            int p = tpos[t * BATCH + b];
            s_p[t] = p;
            s_sign[t] = 1.f - 2.f * (float)bits[p];
            bits[p] ^= 1;
        }
    }
    __syncthreads();

    // prefetch W1 row for step 0
    __nv_bfloat16 wv[4];
    {
        const __nv_bfloat16* wrow = g_W1 + (size_t)s_p[0] * HID;
#pragma unroll
        for (int k = 0; k < 4; k++) wv[k] = wrow[tid + k * 256];
    }

    // sync-free main loop; issue next row's loads before consuming this row's
    for (int t = 0; t < STEPS; t++) {
        const int row = t * BATCH + b;
        __nv_bfloat16* dst = g_H1 + (size_t)row * HID;
#pragma unroll
        for (int k = 0; k < 4; k++) {
            int col = tid + k * 256;
            dst[col] = __float2bfloat16(fmaxf(z[k] + bb[k], 0.f));
        }
        const float sg = s_sign[t];
        float wf[4];
#pragma unroll
        for (int k = 0; k < 4; k++) wf[k] = __bfloat162float(wv[k]);
        if (t + 1 < STEPS) {
            const __nv_bfloat16* wnext = g_W1 + (size_t)s_p[t + 1] * HID;
#pragma unroll
            for (int k = 0; k < 4; k++) wv[k] = wnext[tid + k * 256];
        }
#pragma unroll
        for (int k = 0; k < 4; k++) z[k] += sg * wf[k];
    }
}

// ---------------- assemble outputs --------------------------------------------
__global__ void finalize_kernel(const float* __restrict__ init,
                                const int* __restrict__ tpos,
                                float* __restrict__ out) {
    int b = blockIdx.x;
    const int tid = threadIdx.x;
    const float* src = init + (size_t)b * DIM;
    float* frow = out + OUT_FINAL + (size_t)b * DIM;
    float* vrow = out + OUT_VINIT + (size_t)b * DIM;
    for (int i = tid; i < DIM; i += blockDim.x) {
        float v = src[i];
        frow[i] = v;
        vrow[i] = v;
    }
    // parallel total_log: warp 0 handles the 32 steps, one per lane
    float part = 0.f;
    if (tid < 32) {
        int r = tid * BATCH + b;
        part = g_tl[r] - __logf(g_sum[r]);
#pragma unroll
        for (int o = 16; o; o >>= 1)
            part += __shfl_xor_sync(0xffffffffu, part, o);
    }
    __syncthreads();
    if (tid == 0) {
        for (int s = 0; s < STEPS; s++) {
            int p = tpos[s * BATCH + b];
            frow[p] = 1.0f - frow[p];
        }
        out[OUT_TLOG + b] = part;
    }
}

// ---------------- launch --------------------------------------------------------
extern "C" void kernel_launch(void* const* d_in, const int* in_sizes, int n_in,
                              void* d_out, int out_size) {
    const float* init = (const float*)d_in[0];
    const int*   tpos = (const int*)d_in[1];
    const float* W1   = (const float*)d_in[2];
    const float* b1   = (const float*)d_in[3];
    const float* W2   = (const float*)d_in[4];
    const float* b2   = (const float*)d_in[5];
    const float* W3   = (const float*)d_in[6];
    const float* b3   = (const float*)d_in[7];
    float* out = (float*)d_out;

    static __nv_bfloat16 *pW1 = nullptr, *pW2, *pW3, *pX0, *pH1, *pH2;
    static float *pZ1;
    if (!pW1) {
        cudaGetSymbolAddress((void**)&pW1, g_W1);
        cudaGetSymbolAddress((void**)&pW2, g_W2);
        cudaGetSymbolAddress((void**)&pW3, g_W3);
        cudaGetSymbolAddress((void**)&pX0, g_X0);
        cudaGetSymbolAddress((void**)&pH1, g_H1);
        cudaGetSymbolAddress((void**)&pH2, g_H2);
        cudaGetSymbolAddress((void**)&pZ1, g_Z1);
        cudaFuncSetAttribute(gemm_kernel<0>,
            cudaFuncAttributeMaxDynamicSharedMemorySize, GEMM_SMEM_BYTES);
        cudaFuncSetAttribute(gemm_kernel<2>,
            cudaFuncAttributeMaxDynamicSharedMemorySize, GEMM_SMEM_BYTES);
        cudaFuncSetAttribute(gemm_kernel<3>,
            cudaFuncAttributeMaxDynamicSharedMemorySize, GEMM_SMEM_BYTES);
    }

    // merged vectorized prep (weights, X0, sum zeroing, delta output)
    // grid must cover X0: BATCH*DIM elems at 4/thread = 2048 blocks
    prep_all_kernel<<<BATCH * DIM / (256 * 4), 256>>>(W1, W2, W3, init, tpos, out);

    // z1_base = X0 @ W1 (fp32 raw)
    gemm_kernel<0><<<dim3(8, BATCH / 128), 256, GEMM_SMEM_BYTES>>>(
        pX0, pW1, nullptr, nullptr, pZ1, nullptr);
    // incremental layer 1
    h1_kernel<<<BATCH, 256>>>(init, tpos, b1);
    // layer 2: H2 = relu(H1 @ W2 + b2)
    gemm_kernel<2><<<dim3(8, ROWS / 128), 256, GEMM_SMEM_BYTES>>>(
        pH1, pW2, b2, pH2, nullptr, nullptr);
    // layer 3 fused: softmax stats + target gather (no logits store)
    gemm_kernel<3><<<dim3(8, ROWS / 128), 256, GEMM_SMEM_BYTES>>>(
        pH2, pW3, b3, nullptr, nullptr, tpos);

    finalize_kernel<<<BATCH, 256>>>(init, tpos, out);
}